// round 1
// baseline (speedup 1.0000x reference)
#include <cuda_runtime.h>
#include <cuda_bf16.h>

typedef __nv_bfloat16 bf16;

#define NTHREADS 256
#define TILES 8192      // B(2) * 64 * 64
#define GRP 5           // tiles per CTA group -> 125 pixels (pad to 128)
#define WS 136          // bf16 row stride for 128-col matrices (conflict-avoid pad)

// ---------------- precomputed combined weights (bf16) ----------------
__device__ __align__(16) bf16 g_Wch[128 * 128];   // (Wfuse[:, :128] @ Whpw)[o][c]
__device__ __align__(16) bf16 g_Wcv[128 * 128];   // (Wfuse[:,128:] @ Wvpw)[o][c]
__device__ __align__(16) bf16 g_Wdm1[32 * 128];
__device__ __align__(16) bf16 g_Wdm2[128 * 32];

__global__ void prep_kernel(const float* __restrict__ whpw, const float* __restrict__ wvpw,
                            const float* __restrict__ wdm1, const float* __restrict__ wdm2,
                            const float* __restrict__ wfuse) {
  int o = blockIdx.x, c = threadIdx.x;
  float sh = 0.f, sv = 0.f;
  for (int m = 0; m < 128; ++m) {
    sh += wfuse[o * 256 + m]       * whpw[m * 128 + c];
    sv += wfuse[o * 256 + 128 + m] * wvpw[m * 128 + c];
  }
  g_Wch[o * 128 + c] = __float2bfloat16(sh);
  g_Wcv[o * 128 + c] = __float2bfloat16(sv);
  if (o < 32) g_Wdm1[o * 128 + c] = __float2bfloat16(wdm1[o * 128 + c]);
  if (c < 32) g_Wdm2[o * 32 + c]  = __float2bfloat16(wdm2[o * 32 + c]);
}

// ---------------- helpers ----------------
__device__ __forceinline__ void mma16816(float* d, const unsigned* a, unsigned b0, unsigned b1) {
  asm volatile(
      "mma.sync.aligned.m16n8k16.row.col.f32.bf16.bf16.f32 "
      "{%0,%1,%2,%3}, {%4,%5,%6,%7}, {%8,%9}, {%0,%1,%2,%3};\n"
      : "+f"(d[0]), "+f"(d[1]), "+f"(d[2]), "+f"(d[3])
      : "r"(a[0]), "r"(a[1]), "r"(a[2]), "r"(a[3]), "r"(b0), "r"(b1));
}

__device__ __forceinline__ unsigned pack2(float a, float b) {
  unsigned lo = (unsigned)__bfloat16_as_ushort(__float2bfloat16(a));
  unsigned hi = (unsigned)__bfloat16_as_ushort(__float2bfloat16(b));
  return lo | (hi << 16);
}
__device__ __forceinline__ float lo2f(unsigned u) {
  return __bfloat162float(__ushort_as_bfloat16((unsigned short)(u & 0xffffu)));
}
__device__ __forceinline__ float hi2f(unsigned u) {
  return __bfloat162float(__ushort_as_bfloat16((unsigned short)(u >> 16)));
}
__device__ __forceinline__ float lrelu(float x) { return x > 0.f ? x : 0.1f * x; }
__device__ __forceinline__ float sigmoidf_(float x) { return 1.0f / (1.0f + expf(-x)); }

// smem layout (bytes)
#define OFF_WCH   0
#define OFF_WCV   34816
#define OFF_WDM1  69632
#define OFF_WDM2  78336
#define OFF_WHDW  88576
#define OFF_WVDW  91136
#define OFF_AH    93696
#define OFF_AV    128512
#define OFF_EPI   163328
#define OFF_HID   198144
#define OFF_XT    208384
#define SMEM_TOTAL 222208
#define OFF_OUTS  OFF_AH      /* fp32 [128][132] overlay on Ah+Av (dead after epi GEMM) */

__global__ __launch_bounds__(NTHREADS, 1)
void epi_kernel(const float* __restrict__ x,
                const float* __restrict__ whdw, const float* __restrict__ wvdw,
                const float* __restrict__ scale,
                float* __restrict__ out) {
  extern __shared__ char smem[];
  bf16*  Wch_s  = (bf16*)(smem + OFF_WCH);    // [128][WS]
  bf16*  Wcv_s  = (bf16*)(smem + OFF_WCV);    // [128][WS]
  bf16*  Wdm1_s = (bf16*)(smem + OFF_WDM1);   // [32][WS]
  bf16*  Wdm2_s = (bf16*)(smem + OFF_WDM2);   // [128][40]
  float* whdw_s = (float*)(smem + OFF_WHDW);  // [640]
  float* wvdw_s = (float*)(smem + OFF_WVDW);  // [640]
  bf16*  Ah     = (bf16*)(smem + OFF_AH);     // [128][WS]
  bf16*  Av     = (bf16*)(smem + OFF_AV);     // [128][WS]
  bf16*  Epi    = (bf16*)(smem + OFF_EPI);    // [128][WS]
  bf16*  Hid    = (bf16*)(smem + OFF_HID);    // [128][40]
  float* xt     = (float*)(smem + OFF_XT);    // [128][27]
  float* outs   = (float*)(smem + OFF_OUTS);  // [128][132]

  const int tid  = threadIdx.x;
  const int wid  = tid >> 5;
  const int lane = tid & 31;
  const int g    = lane >> 2;   // groupID
  const int tg   = lane & 3;    // threadID_in_group

  // ---------- Phase 0: stage weights into smem (vectorized) ----------
  {
    const uint4* src_h = (const uint4*)g_Wch;
    const uint4* src_v = (const uint4*)g_Wcv;
    for (int f = tid; f < 2048; f += NTHREADS) {           // 2048 * 8 bf16 = 16384
      int n = f >> 4, k8 = (f & 15) << 3;
      *(uint4*)(Wch_s + n * WS + k8) = src_h[f];
      *(uint4*)(Wcv_s + n * WS + k8) = src_v[f];
    }
    const uint4* src_d1 = (const uint4*)g_Wdm1;
    for (int f = tid; f < 512; f += NTHREADS) {            // 32*128 bf16
      int n = f >> 4, k8 = (f & 15) << 3;
      *(uint4*)(Wdm1_s + n * WS + k8) = src_d1[f];
    }
    const uint2* src_d2 = (const uint2*)g_Wdm2;
    for (int f = tid; f < 1024; f += NTHREADS) {           // 128*32 bf16 in uint2 (4 bf16)
      int n = f >> 3, k4 = (f & 7) << 2;
      *(uint2*)(Wdm2_s + n * 40 + k4) = src_d2[f];
    }
    const float4* s1 = (const float4*)whdw;
    const float4* s2 = (const float4*)wvdw;
    for (int f = tid; f < 160; f += NTHREADS) {
      ((float4*)whdw_s)[f] = s1[f];
      ((float4*)wvdw_s)[f] = s2[f];
    }
  }

  const int t0   = blockIdx.x * GRP;
  const int nval = min(GRP, TILES - t0);

  // zero pad rows of Ah/Av (rows >= nval*25)
  for (int f = tid; f < (128 - nval * 25) * 128; f += NTHREADS) {
    int r = nval * 25 + (f >> 7), k = f & 127;
    Ah[r * WS + k] = __float2bfloat16(0.f);
    Av[r * WS + k] = __float2bfloat16(0.f);
  }
  __syncthreads();

  // ---------- Phase 1: per-tile load + depthwise conv + lrelu -> bf16 A ----------
  for (int i = 0; i < nval; ++i) {
    int t = t0 + i;
    int b = t >> 12, rem = t & 4095, hh = rem >> 6, ww = rem & 63;
    int base = b * 128 * 102400 + hh * 5 * 320 + ww * 5;

    // coalesced-ish staged load, batched x4 for MLP
    for (int f0 = 0; f0 < 3200; f0 += NTHREADS * 4) {
      float v[4]; int sidx[4];
      #pragma unroll
      for (int k2 = 0; k2 < 4; ++k2) {
        int f = f0 + tid + k2 * NTHREADS;
        if (f < 3200) {
          int c = f / 25, q = f % 25, u = q / 5, vv = q % 5;
          sidx[k2] = c * 27 + q;
          v[k2] = x[base + c * 102400 + u * 320 + vv];
        } else sidx[k2] = -1;
      }
      #pragma unroll
      for (int k2 = 0; k2 < 4; ++k2)
        if (sidx[k2] >= 0) xt[sidx[k2]] = v[k2];
    }
    __syncthreads();

    {
      int c = tid & 127, half = tid >> 7;
      float wh0 = whdw_s[c*5+0], wh1 = whdw_s[c*5+1], wh2 = whdw_s[c*5+2],
            wh3 = whdw_s[c*5+3], wh4 = whdw_s[c*5+4];
      float wv0 = wvdw_s[c*5+0], wv1 = wvdw_s[c*5+1], wv2 = wvdw_s[c*5+2],
            wv3 = wvdw_s[c*5+3], wv4 = wvdw_s[c*5+4];
      const float* xr = xt + c * 27;
      for (int q = half; q < 25; q += 2) {
        int u = q / 5, v = q % 5;
        float ah = 0.f, av = 0.f;
        // horizontal: taps at v-2..v+2 (zero pad outside [0,5))
        if (v - 2 >= 0) ah += xr[u*5 + v - 2] * wh0;
        if (v - 1 >= 0) ah += xr[u*5 + v - 1] * wh1;
        ah += xr[u*5 + v] * wh2;
        if (v + 1 < 5)  ah += xr[u*5 + v + 1] * wh3;
        if (v + 2 < 5)  ah += xr[u*5 + v + 2] * wh4;
        // vertical
        if (u - 2 >= 0) av += xr[(u-2)*5 + v] * wv0;
        if (u - 1 >= 0) av += xr[(u-1)*5 + v] * wv1;
        av += xr[u*5 + v] * wv2;
        if (u + 1 < 5)  av += xr[(u+1)*5 + v] * wv3;
        if (u + 2 < 5)  av += xr[(u+2)*5 + v] * wv4;
        ah = lrelu(ah); av = lrelu(av);
        int p = i * 25 + q;
        Ah[p * WS + c] = __float2bfloat16(ah);
        Av[p * WS + c] = __float2bfloat16(av);
      }
    }
    __syncthreads();
  }

  // ---------- Phase 2: epi GEMM  epi = Ah*Wch^T + Av*Wcv^T   (M128 N128 K256) ----------
  const int wm = wid >> 1;   // 0..3 -> 32-row band
  const int wn = wid & 1;    // 0..1 -> 64-col band
  float acc[2][8][4];
  #pragma unroll
  for (int a = 0; a < 2; ++a)
    #pragma unroll
    for (int b2 = 0; b2 < 8; ++b2)
      #pragma unroll
      for (int c2 = 0; c2 < 4; ++c2) acc[a][b2][c2] = 0.f;

  #pragma unroll
  for (int src = 0; src < 2; ++src) {
    const bf16* AS = src ? Av : Ah;
    const bf16* BS = src ? Wcv_s : Wch_s;
    #pragma unroll
    for (int kk = 0; kk < 8; ++kk) {
      int k0 = kk * 16;
      unsigned a[2][4];
      #pragma unroll
      for (int mi = 0; mi < 2; ++mi) {
        int r = wm * 32 + mi * 16 + g;
        a[mi][0] = *(const unsigned*)(AS + r * WS + k0 + tg * 2);
        a[mi][1] = *(const unsigned*)(AS + (r + 8) * WS + k0 + tg * 2);
        a[mi][2] = *(const unsigned*)(AS + r * WS + k0 + 8 + tg * 2);
        a[mi][3] = *(const unsigned*)(AS + (r + 8) * WS + k0 + 8 + tg * 2);
      }
      #pragma unroll
      for (int ni = 0; ni < 8; ++ni) {
        int n = wn * 64 + ni * 8 + g;
        unsigned b0 = *(const unsigned*)(BS + n * WS + k0 + tg * 2);
        unsigned b1 = *(const unsigned*)(BS + n * WS + k0 + 8 + tg * 2);
        mma16816(acc[0][ni], a[0], b0, b1);
        mma16816(acc[1][ni], a[1], b0, b1);
      }
    }
  }
  // store epi as bf16
  #pragma unroll
  for (int mi = 0; mi < 2; ++mi)
    #pragma unroll
    for (int ni = 0; ni < 8; ++ni) {
      int r  = wm * 32 + mi * 16 + g;
      int c0 = wn * 64 + ni * 8 + tg * 2;
      *(unsigned*)(Epi + r * WS + c0)       = pack2(acc[mi][ni][0], acc[mi][ni][1]);
      *(unsigned*)(Epi + (r + 8) * WS + c0) = pack2(acc[mi][ni][2], acc[mi][ni][3]);
    }
  __syncthreads();

  // ---------- Phase 3: hid = lrelu(epi * Wdm1^T)   (M128 N32 K128) ----------
  {
    float hacc[4][4];
    #pragma unroll
    for (int a = 0; a < 4; ++a)
      #pragma unroll
      for (int b2 = 0; b2 < 4; ++b2) hacc[a][b2] = 0.f;
    int rb = wid * 16;
    #pragma unroll
    for (int kk = 0; kk < 8; ++kk) {
      int k0 = kk * 16;
      unsigned a[4];
      int r = rb + g;
      a[0] = *(const unsigned*)(Epi + r * WS + k0 + tg * 2);
      a[1] = *(const unsigned*)(Epi + (r + 8) * WS + k0 + tg * 2);
      a[2] = *(const unsigned*)(Epi + r * WS + k0 + 8 + tg * 2);
      a[3] = *(const unsigned*)(Epi + (r + 8) * WS + k0 + 8 + tg * 2);
      #pragma unroll
      for (int ni = 0; ni < 4; ++ni) {
        int n = ni * 8 + g;
        unsigned b0 = *(const unsigned*)(Wdm1_s + n * WS + k0 + tg * 2);
        unsigned b1 = *(const unsigned*)(Wdm1_s + n * WS + k0 + 8 + tg * 2);
        mma16816(hacc[ni], a, b0, b1);
      }
    }
    #pragma unroll
    for (int ni = 0; ni < 4; ++ni) {
      int r = rb + g, c0 = ni * 8 + tg * 2;
      *(unsigned*)(Hid + r * 40 + c0)       = pack2(lrelu(hacc[ni][0]), lrelu(hacc[ni][1]));
      *(unsigned*)(Hid + (r + 8) * 40 + c0) = pack2(lrelu(hacc[ni][2]), lrelu(hacc[ni][3]));
    }
  }
  __syncthreads();

  // ---------- Phase 4: dwgt = sigmoid(hid * Wdm2^T); outs = scale*epi*dwgt ----------
  {
    float dacc[2][8][4];
    #pragma unroll
    for (int a = 0; a < 2; ++a)
      #pragma unroll
      for (int b2 = 0; b2 < 8; ++b2)
        #pragma unroll
        for (int c2 = 0; c2 < 4; ++c2) dacc[a][b2][c2] = 0.f;

    #pragma unroll
    for (int kk = 0; kk < 2; ++kk) {
      int k0 = kk * 16;
      unsigned a[2][4];
      #pragma unroll
      for (int mi = 0; mi < 2; ++mi) {
        int r = wm * 32 + mi * 16 + g;
        a[mi][0] = *(const unsigned*)(Hid + r * 40 + k0 + tg * 2);
        a[mi][1] = *(const unsigned*)(Hid + (r + 8) * 40 + k0 + tg * 2);
        a[mi][2] = *(const unsigned*)(Hid + r * 40 + k0 + 8 + tg * 2);
        a[mi][3] = *(const unsigned*)(Hid + (r + 8) * 40 + k0 + 8 + tg * 2);
      }
      #pragma unroll
      for (int ni = 0; ni < 8; ++ni) {
        int n = wn * 64 + ni * 8 + g;
        unsigned b0 = *(const unsigned*)(Wdm2_s + n * 40 + k0 + tg * 2);
        unsigned b1 = *(const unsigned*)(Wdm2_s + n * 40 + k0 + 8 + tg * 2);
        mma16816(dacc[0][ni], a[0], b0, b1);
        mma16816(dacc[1][ni], a[1], b0, b1);
      }
    }
    float sc = scale[0];
    #pragma unroll
    for (int mi = 0; mi < 2; ++mi)
      #pragma unroll
      for (int ni = 0; ni < 8; ++ni) {
        int r  = wm * 32 + mi * 16 + g;
        int c0 = wn * 64 + ni * 8 + tg * 2;
        unsigned e01 = *(const unsigned*)(Epi + r * WS + c0);
        unsigned e23 = *(const unsigned*)(Epi + (r + 8) * WS + c0);
        outs[r * 132 + c0]           = sc * lo2f(e01) * sigmoidf_(dacc[mi][ni][0]);
        outs[r * 132 + c0 + 1]       = sc * hi2f(e01) * sigmoidf_(dacc[mi][ni][1]);
        outs[(r + 8) * 132 + c0]     = sc * lo2f(e23) * sigmoidf_(dacc[mi][ni][2]);
        outs[(r + 8) * 132 + c0 + 1] = sc * hi2f(e23) * sigmoidf_(dacc[mi][ni][3]);
      }
  }
  __syncthreads();

  // ---------- Phase 5: out = x + outs (coalesced, batched x4) ----------
  for (int i = 0; i < nval; ++i) {
    int t = t0 + i;
    int b = t >> 12, rem = t & 4095, hh = rem >> 6, ww = rem & 63;
    int base = b * 128 * 102400 + hh * 5 * 320 + ww * 5;
    for (int f0 = 0; f0 < 3200; f0 += NTHREADS * 4) {
      float xv[4], ov[4]; int gi[4];
      #pragma unroll
      for (int k2 = 0; k2 < 4; ++k2) {
        int f = f0 + tid + k2 * NTHREADS;
        if (f < 3200) {
          int c = f / 25, q = f % 25, u = q / 5, vv = q % 5;
          gi[k2] = base + c * 102400 + u * 320 + vv;
          xv[k2] = x[gi[k2]];
          ov[k2] = outs[(i * 25 + q) * 132 + c];
        } else gi[k2] = -1;
      }
      #pragma unroll
      for (int k2 = 0; k2 < 4; ++k2)
        if (gi[k2] >= 0) out[gi[k2]] = xv[k2] + ov[k2];
    }
  }
}

extern "C" void kernel_launch(void* const* d_in, const int* in_sizes, int n_in,
                              void* d_out, int out_size) {
  const float* x     = (const float*)d_in[0];
  const float* whdw  = (const float*)d_in[1];
  const float* whpw  = (const float*)d_in[2];
  const float* wvdw  = (const float*)d_in[3];
  const float* wvpw  = (const float*)d_in[4];
  const float* wdm1  = (const float*)d_in[5];
  const float* wdm2  = (const float*)d_in[6];
  const float* wfuse = (const float*)d_in[7];
  const float* scale = (const float*)d_in[8];
  float* out = (float*)d_out;

  prep_kernel<<<128, 128>>>(whpw, wvpw, wdm1, wdm2, wfuse);

  cudaFuncSetAttribute(epi_kernel, cudaFuncAttributeMaxDynamicSharedMemorySize, SMEM_TOTAL);
  int groups = (TILES + GRP - 1) / GRP;   // 1639
  epi_kernel<<<groups, NTHREADS, SMEM_TOTAL>>>(x, whdw, wvdw, scale, out);
}

// round 2
// speedup vs baseline: 1.9247x; 1.9247x over previous
#include <cuda_runtime.h>
#include <cuda_bf16.h>

typedef __nv_bfloat16 bf16;

#define NT 512
#define TILES 8192      // B(2) * 64 * 64
#define GRP 5           // tiles per CTA -> 125 rows (pad to 128)
#define SA 264          // A row stride (bf16): 132 words == 4 mod 32 -> conflict-free frags
#define SE 136          // Epi row stride (bf16)
#define SO 133          // outs row stride (fp32): 133 == 5 mod 32 -> conflict-free phase-5 reads

// ---------------- precomputed combined weights (bf16) ----------------
__device__ __align__(16) bf16 g_Wc[128 * 256];    // [o][k]: k<128 = Wfuse_h@Whpw, k>=128 = Wfuse_v@Wvpw
__device__ __align__(16) bf16 g_Wdm1[32 * 128];
__device__ __align__(16) bf16 g_Wdm2[128 * 32];

__global__ void prep_kernel(const float* __restrict__ whpw, const float* __restrict__ wvpw,
                            const float* __restrict__ wdm1, const float* __restrict__ wdm2,
                            const float* __restrict__ wfuse) {
  int o = blockIdx.x, c = threadIdx.x;
  float sh = 0.f, sv = 0.f;
  for (int m = 0; m < 128; ++m) {
    sh += wfuse[o * 256 + m]       * whpw[m * 128 + c];
    sv += wfuse[o * 256 + 128 + m] * wvpw[m * 128 + c];
  }
  g_Wc[o * 256 + c]       = __float2bfloat16(sh);
  g_Wc[o * 256 + 128 + c] = __float2bfloat16(sv);
  if (o < 32) g_Wdm1[o * 128 + c] = __float2bfloat16(wdm1[o * 128 + c]);
  if (c < 32) g_Wdm2[o * 32 + c]  = __float2bfloat16(wdm2[o * 32 + c]);
}

// ---------------- helpers ----------------
__device__ __forceinline__ void mma16816(float* d, const unsigned* a, unsigned b0, unsigned b1) {
  asm volatile(
      "mma.sync.aligned.m16n8k16.row.col.f32.bf16.bf16.f32 "
      "{%0,%1,%2,%3}, {%4,%5,%6,%7}, {%8,%9}, {%0,%1,%2,%3};\n"
      : "+f"(d[0]), "+f"(d[1]), "+f"(d[2]), "+f"(d[3])
      : "r"(a[0]), "r"(a[1]), "r"(a[2]), "r"(a[3]), "r"(b0), "r"(b1));
}
__device__ __forceinline__ unsigned pack2(float a, float b) {
  unsigned lo = (unsigned)__bfloat16_as_ushort(__float2bfloat16(a));
  unsigned hi = (unsigned)__bfloat16_as_ushort(__float2bfloat16(b));
  return lo | (hi << 16);
}
__device__ __forceinline__ float lo2f(unsigned u) {
  return __bfloat162float(__ushort_as_bfloat16((unsigned short)(u & 0xffffu)));
}
__device__ __forceinline__ float hi2f(unsigned u) {
  return __bfloat162float(__ushort_as_bfloat16((unsigned short)(u >> 16)));
}
__device__ __forceinline__ float lrelu(float x) { return x > 0.f ? x : 0.1f * x; }
__device__ __forceinline__ float sigmoidf_(float x) { return 1.0f / (1.0f + expf(-x)); }

// ---------------- smem layout (bytes) ----------------
// region 0 (union): A bf16 [128][SA] (67584)  |  outs fp32 [128][SO] (68096)
#define OFF_A     0
#define OFF_OUTS  0
#define SZ_U0     68096
// region 1: Wc bf16 [128][SA] (67584)
#define OFF_WC    68096
// region 2 (overlay): XT fp32 [5][128][27] (69120) THEN {Epi [128][SE] 34816 | Wdm1 [32][SE] 8704 | Wdm2 [128][40] 10240 | Hid [128][40] 10240}
#define OFF_OVL   135680
#define OFF_EPI   OFF_OVL
#define OFF_WDM1  (OFF_OVL + 34816)
#define OFF_WDM2  (OFF_OVL + 43520)
#define OFF_HID   (OFF_OVL + 53760)
// region 3: depthwise weights fp32 [2][640]
#define OFF_DWW   204800
#define SMEM_TOTAL 209920

__global__ __launch_bounds__(NT, 1)
void epi_kernel(const float* __restrict__ x,
                const float* __restrict__ whdw, const float* __restrict__ wvdw,
                const float* __restrict__ scale,
                float* __restrict__ out) {
  extern __shared__ char smem[];
  bf16*  A      = (bf16*)(smem + OFF_A);      // [128][SA]  (cols 0..127 = ah, 128..255 = av)
  float* outs   = (float*)(smem + OFF_OUTS);  // [128][SO]
  bf16*  Wc_s   = (bf16*)(smem + OFF_WC);     // [128][SA]
  float* XT     = (float*)(smem + OFF_OVL);   // [5][128][27]
  bf16*  Epi    = (bf16*)(smem + OFF_EPI);    // [128][SE]
  bf16*  Wdm1_s = (bf16*)(smem + OFF_WDM1);   // [32][SE]
  bf16*  Wdm2_s = (bf16*)(smem + OFF_WDM2);   // [128][40]
  bf16*  Hid    = (bf16*)(smem + OFF_HID);    // [128][40]
  float* whdw_s = (float*)(smem + OFF_DWW);   // [640]
  float* wvdw_s = (float*)(smem + OFF_DWW + 2560);

  const int tid  = threadIdx.x;
  const int wid  = tid >> 5;
  const int lane = tid & 31;
  const int g    = lane >> 2;
  const int tg   = lane & 3;

  const int t0   = blockIdx.x * GRP;
  const int nval = min(GRP, TILES - t0);

  // ---------- Phase 0a: stage combined GEMM weights + dw weights ----------
  {
    const uint4* src = (const uint4*)g_Wc;
    for (int f = tid; f < 4096; f += NT) {          // 128 rows * 32 uint4
      int n = f >> 5, k8 = (f & 31) << 3;
      *(uint4*)(Wc_s + n * SA + k8) = src[f];
    }
    const float4* s1 = (const float4*)whdw;
    const float4* s2 = (const float4*)wvdw;
    for (int f = tid; f < 160; f += NT) {
      ((float4*)whdw_s)[f] = s1[f];
      ((float4*)wvdw_s)[f] = s2[f];
    }
  }

  // ---------- Phase 1a: coalesced load of all tiles into XT ----------
  for (int i = 0; i < nval; ++i) {
    int t = t0 + i;
    int b = t >> 12, hh = (t >> 6) & 63, ww = t & 63;
    int base = b * 13107200 + hh * 1600 + ww * 5;
    for (int e = tid; e < 4096; e += NT) {
      int q = e & 31;
      if (q < 25) {
        int c = e >> 5;
        int u = q / 5, v = q - u * 5;
        XT[i * 3456 + c * 27 + q] = x[base + c * 102400 + u * 320 + v];
      }
    }
  }
  // zero A pad rows (rows >= nval*25), as u32
  {
    unsigned* A32 = (unsigned*)A;
    int padw = (128 - nval * 25) * (SA / 2);
    int base = nval * 25 * (SA / 2);
    for (int f = tid; f < padw; f += NT) A32[base + f] = 0u;
  }
  __syncthreads();

  // ---------- Phase 1b: depthwise conv + lrelu -> A (registers, no div/mod) ----------
  for (int pi = tid; pi < nval * 128; pi += NT) {
    int i = pi >> 7, c = pi & 127;
    float xr[25];
    const float* xp = XT + i * 3456 + c * 27;
    #pragma unroll
    for (int q = 0; q < 25; ++q) xr[q] = xp[q];
    float wh[5], wv[5];
    #pragma unroll
    for (int j = 0; j < 5; ++j) { wh[j] = whdw_s[c * 5 + j]; wv[j] = wvdw_s[c * 5 + j]; }
    bf16* Ar = A + (i * 25) * SA + c;
    #pragma unroll
    for (int u = 0; u < 5; ++u) {
      #pragma unroll
      for (int v = 0; v < 5; ++v) {
        float ah = wh[2] * xr[u * 5 + v];
        float av = wv[2] * xr[u * 5 + v];
        if (v >= 1) ah += wh[1] * xr[u * 5 + v - 1];
        if (v >= 2) ah += wh[0] * xr[u * 5 + v - 2];
        if (v <= 3) ah += wh[3] * xr[u * 5 + v + 1];
        if (v <= 2) ah += wh[4] * xr[u * 5 + v + 2];
        if (u >= 1) av += wv[1] * xr[(u - 1) * 5 + v];
        if (u >= 2) av += wv[0] * xr[(u - 2) * 5 + v];
        if (u <= 3) av += wv[3] * xr[(u + 1) * 5 + v];
        if (u <= 2) av += wv[4] * xr[(u + 2) * 5 + v];
        int q = u * 5 + v;
        Ar[q * SA]       = __float2bfloat16(lrelu(ah));
        Ar[q * SA + 128] = __float2bfloat16(lrelu(av));
      }
    }
  }
  __syncthreads();

  // ---------- Phase 0b: stage Wdm1/Wdm2 (XT now dead; before phase-3 sync) ----------
  {
    const uint4* s1 = (const uint4*)g_Wdm1;
    for (int f = tid; f < 512; f += NT) {           // 32*128/8
      int n = f >> 4, k8 = (f & 15) << 3;
      *(uint4*)(Wdm1_s + n * SE + k8) = s1[f];
    }
    const uint4* s2 = (const uint4*)g_Wdm2;
    for (int f = tid; f < 512; f += NT) {           // 128*32/8
      int n = f >> 2, k8 = (f & 3) << 3;
      *(uint4*)(Wdm2_s + n * 40 + k8) = s2[f];
    }
  }

  // ---------- Phase 2: epi = A @ Wc^T   (M128 N128 K256), 16 warps 32x32 ----------
  const int wm = wid >> 2;
  const int wn = wid & 3;
  float acc[2][4][4];
  #pragma unroll
  for (int a = 0; a < 2; ++a)
    #pragma unroll
    for (int b2 = 0; b2 < 4; ++b2)
      #pragma unroll
      for (int c2 = 0; c2 < 4; ++c2) acc[a][b2][c2] = 0.f;

  #pragma unroll
  for (int kk = 0; kk < 16; ++kk) {
    int k0 = kk * 16;
    unsigned afr[2][4];
    #pragma unroll
    for (int mi = 0; mi < 2; ++mi) {
      int r = wm * 32 + mi * 16 + g;
      afr[mi][0] = *(const unsigned*)(A + r * SA + k0 + tg * 2);
      afr[mi][1] = *(const unsigned*)(A + (r + 8) * SA + k0 + tg * 2);
      afr[mi][2] = *(const unsigned*)(A + r * SA + k0 + 8 + tg * 2);
      afr[mi][3] = *(const unsigned*)(A + (r + 8) * SA + k0 + 8 + tg * 2);
    }
    #pragma unroll
    for (int ni = 0; ni < 4; ++ni) {
      int n = wn * 32 + ni * 8 + g;
      unsigned b0 = *(const unsigned*)(Wc_s + n * SA + k0 + tg * 2);
      unsigned b1 = *(const unsigned*)(Wc_s + n * SA + k0 + 8 + tg * 2);
      mma16816(acc[0][ni], afr[0], b0, b1);
      mma16816(acc[1][ni], afr[1], b0, b1);
    }
  }
  // pack epi to bf16 regs + store to smem for phase 3
  unsigned epk[2][4][2];
  #pragma unroll
  for (int mi = 0; mi < 2; ++mi)
    #pragma unroll
    for (int ni = 0; ni < 4; ++ni) {
      epk[mi][ni][0] = pack2(acc[mi][ni][0], acc[mi][ni][1]);
      epk[mi][ni][1] = pack2(acc[mi][ni][2], acc[mi][ni][3]);
      int r  = wm * 32 + mi * 16 + g;
      int c0 = wn * 32 + ni * 8 + tg * 2;
      *(unsigned*)(Epi + r * SE + c0)       = epk[mi][ni][0];
      *(unsigned*)(Epi + (r + 8) * SE + c0) = epk[mi][ni][1];
    }
  __syncthreads();

  // ---------- Phase 3: hid = lrelu(epi @ Wdm1^T)  (M128 N32 K128), warps 0..7 ----------
  if (wid < 8) {
    int rb = wid * 16;
    float hacc[4][4];
    #pragma unroll
    for (int a = 0; a < 4; ++a)
      #pragma unroll
      for (int b2 = 0; b2 < 4; ++b2) hacc[a][b2] = 0.f;
    #pragma unroll
    for (int kk = 0; kk < 8; ++kk) {
      int k0 = kk * 16;
      unsigned afr[4];
      int r = rb + g;
      afr[0] = *(const unsigned*)(Epi + r * SE + k0 + tg * 2);
      afr[1] = *(const unsigned*)(Epi + (r + 8) * SE + k0 + tg * 2);
      afr[2] = *(const unsigned*)(Epi + r * SE + k0 + 8 + tg * 2);
      afr[3] = *(const unsigned*)(Epi + (r + 8) * SE + k0 + 8 + tg * 2);
      #pragma unroll
      for (int ni = 0; ni < 4; ++ni) {
        int n = ni * 8 + g;
        unsigned b0 = *(const unsigned*)(Wdm1_s + n * SE + k0 + tg * 2);
        unsigned b1 = *(const unsigned*)(Wdm1_s + n * SE + k0 + 8 + tg * 2);
        mma16816(hacc[ni], afr, b0, b1);
      }
    }
    #pragma unroll
    for (int ni = 0; ni < 4; ++ni) {
      int r = rb + g, c0 = ni * 8 + tg * 2;
      *(unsigned*)(Hid + r * 40 + c0)       = pack2(lrelu(hacc[ni][0]), lrelu(hacc[ni][1]));
      *(unsigned*)(Hid + (r + 8) * 40 + c0) = pack2(lrelu(hacc[ni][2]), lrelu(hacc[ni][3]));
    }
  }
  __syncthreads();

  // ---------- Phase 4: dwgt = sigmoid(hid @ Wdm2^T); outs = scale*epi*dwgt ----------
  {
    float dacc[2][4][4];
    #pragma unroll
    for (int a = 0; a < 2; ++a)
      #pragma unroll
      for (int b2 = 0; b2 < 4; ++b2)
        #pragma unroll
        for (int c2 = 0; c2 < 4; ++c2) dacc[a][b2][c2] = 0.f;

    #pragma unroll
    for (int kk = 0; kk < 2; ++kk) {
      int k0 = kk * 16;
      unsigned afr[2][4];
      #pragma unroll
      for (int mi = 0; mi < 2; ++mi) {
        int r = wm * 32 + mi * 16 + g;
        afr[mi][0] = *(const unsigned*)(Hid + r * 40 + k0 + tg * 2);
        afr[mi][1] = *(const unsigned*)(Hid + (r + 8) * 40 + k0 + tg * 2);
        afr[mi][2] = *(const unsigned*)(Hid + r * 40 + k0 + 8 + tg * 2);
        afr[mi][3] = *(const unsigned*)(Hid + (r + 8) * 40 + k0 + 8 + tg * 2);
      }
      #pragma unroll
      for (int ni = 0; ni < 4; ++ni) {
        int n = wn * 32 + ni * 8 + g;
        unsigned b0 = *(const unsigned*)(Wdm2_s + n * 40 + k0 + tg * 2);
        unsigned b1 = *(const unsigned*)(Wdm2_s + n * 40 + k0 + 8 + tg * 2);
        mma16816(dacc[0][ni], afr[0], b0, b1);
        mma16816(dacc[1][ni], afr[1], b0, b1);
      }
    }
    float sc = scale[0];
    #pragma unroll
    for (int mi = 0; mi < 2; ++mi)
      #pragma unroll
      for (int ni = 0; ni < 4; ++ni) {
        int r  = wm * 32 + mi * 16 + g;
        int c0 = wn * 32 + ni * 8 + tg * 2;
        unsigned e01 = epk[mi][ni][0], e23 = epk[mi][ni][1];
        outs[r * SO + c0]           = sc * lo2f(e01) * sigmoidf_(dacc[mi][ni][0]);
        outs[r * SO + c0 + 1]       = sc * hi2f(e01) * sigmoidf_(dacc[mi][ni][1]);
        outs[(r + 8) * SO + c0]     = sc * lo2f(e23) * sigmoidf_(dacc[mi][ni][2]);
        outs[(r + 8) * SO + c0 + 1] = sc * hi2f(e23) * sigmoidf_(dacc[mi][ni][3]);
      }
  }
  __syncthreads();

  // ---------- Phase 5: out = x + outs (coalesced, shift/mask indexing) ----------
  for (int i = 0; i < nval; ++i) {
    int t = t0 + i;
    int b = t >> 12, hh = (t >> 6) & 63, ww = t & 63;
    int base = b * 13107200 + hh * 1600 + ww * 5;
    for (int e = tid; e < 4096; e += NT) {
      int q = e & 31;
      if (q < 25) {
        int c = e >> 5;
        int u = q / 5, v = q - u * 5;
        int gi = base + c * 102400 + u * 320 + v;
        out[gi] = x[gi] + outs[(i * 25 + q) * SO + c];
      }
    }
  }
}

extern "C" void kernel_launch(void* const* d_in, const int* in_sizes, int n_in,
                              void* d_out, int out_size) {
  const float* x     = (const float*)d_in[0];
  const float* whdw  = (const float*)d_in[1];
  const float* whpw  = (const float*)d_in[2];
  const float* wvdw  = (const float*)d_in[3];
  const float* wvpw  = (const float*)d_in[4];
  const float* wdm1  = (const float*)d_in[5];
  const float* wdm2  = (const float*)d_in[6];
  const float* wfuse = (const float*)d_in[7];
  const float* scale = (const float*)d_in[8];
  float* out = (float*)d_out;

  prep_kernel<<<128, 128>>>(whpw, wvpw, wdm1, wdm2, wfuse);

  cudaFuncSetAttribute(epi_kernel, cudaFuncAttributeMaxDynamicSharedMemorySize, SMEM_TOTAL);
  int groups = (TILES + GRP - 1) / GRP;   // 1639
  epi_kernel<<<groups, NT, SMEM_TOTAL>>>(x, whdw, wvdw, scale, out);
}